// round 16
// baseline (speedup 1.0000x reference)
#include <cuda_runtime.h>
#include <cuda_bf16.h>
#include <cuda_fp16.h>
#include <cstdint>

#define BB   4
#define NN   256
#define DIN  128
#define DE   64
#define NH   8
#define DK   16
#define HD   128
#define QR   4     // rows per qkv block
#define QKV_BLOCKS ((BB * NN) / QR)   // 256

// ---------------------------------------------------------------------------
// device-global scratch (no allocations allowed)
// ---------------------------------------------------------------------------
__device__ float g_Q[BB * NN * HD];
__device__ float g_K[BB * NN * HD];   // pre-scaled by DK^-0.5
__device__ float g_V[BB * NN * HD];
__device__ __half g_Bh[2 * HD * DE];  // fp16 W_hi: [n=256][d=64]; n<128 -> WE2 col n, else WE col n-128

#define SMEM_SWZ(off) ((off) ^ (((off) >> 3) & 0x70))

__device__ __forceinline__ uint32_t smem_u32(const void* p) {
    uint32_t a;
    asm("{ .reg .u64 t; cvta.to.shared.u64 t, %1; cvt.u32.u64 %0, t; }" : "=r"(a) : "l"(p));
    return a;
}

// warp-level fp16 MMA (sm_80+, legal on plain sm_103 target)
__device__ __forceinline__ void mma16816(float* c, const uint32_t* a, const uint32_t* b) {
    asm volatile(
        "mma.sync.aligned.m16n8k16.row.col.f32.f16.f16.f32 "
        "{%0,%1,%2,%3}, {%4,%5,%6,%7}, {%8,%9}, {%0,%1,%2,%3};"
        : "+f"(c[0]), "+f"(c[1]), "+f"(c[2]), "+f"(c[3])
        : "r"(a[0]), "r"(a[1]), "r"(a[2]), "r"(a[3]), "r"(b[0]), "r"(b[1]));
}
__device__ __forceinline__ void ldmat_x4(uint32_t* r, uint32_t saddr) {
    asm volatile("ldmatrix.sync.aligned.m8n8.x4.shared.b16 {%0,%1,%2,%3}, [%4];"
        : "=r"(r[0]), "=r"(r[1]), "=r"(r[2]), "=r"(r[3]) : "r"(saddr));
}
__device__ __forceinline__ uint32_t pack_h2(float2 v) {
    const __half2 h2 = __float22half2_rn(v);
    return *(const uint32_t*)&h2;
}

// ---------------------------------------------------------------------------
// SMEM layout (dynamic) — 3 CTAs/SM
// ---------------------------------------------------------------------------
#define SM_B       0                       // W_hi fp16 swizzled: 256 rows x 128B = 32768
#define SM_QK      32768                   // 256*9*4 = 9216
#define SM_AM      41984                   // 256*4
#define SM_QROW    43008                   // 128*4
#define SM_WDEN    43520                   // 8*128*4 = 4096
#define SM_WOUT    47616                   // 8*128*4 = 4096
#define SMEM_TOTAL 51712

// ---------------------------------------------------------------------------
// Kernel 1: QKV projection (+ fused weight-convert blocks).
// ---------------------------------------------------------------------------
__global__ __launch_bounds__(256) void prep_kernel(
    const float* __restrict__ h,
    const float* __restrict__ WQ,
    const float* __restrict__ WK,
    const float* __restrict__ WV,
    const float* __restrict__ WE,
    const float* __restrict__ WE2)
{
    if (blockIdx.x >= QKV_BLOCKS) {
        const int idx = (blockIdx.x - QKV_BLOCKS) * 256 + threadIdx.x;  // 0..16383
        const int n = idx >> 6, d = idx & 63;
        const float* W = (n < HD) ? WE2 : WE;
        g_Bh[idx] = __float2half(W[d * HD + (n & (HD - 1))]);
        return;
    }

    __shared__ float sh[QR][DIN];
    __shared__ float sp[3][3][QR][HD];   // partials for d-quarters 1..3
    const int rb = blockIdx.x * QR;
    const int t  = threadIdx.x;
    const int cp = t & 63;               // col pair -> cols 2cp, 2cp+1
    const int dq = t >> 6;               // d quarter

    ((float*)sh)[t]       = h[rb * DIN + t];
    ((float*)sh)[t + 256] = h[rb * DIN + t + 256];
    __syncthreads();

    float acc[3][QR][2];
    #pragma unroll
    for (int m = 0; m < 3; m++)
        #pragma unroll
        for (int r = 0; r < QR; r++) { acc[m][r][0] = 0.f; acc[m][r][1] = 0.f; }

    const int d0 = dq * 32;
    #pragma unroll 8
    for (int d = 0; d < 32; d++) {
        const float2 wq = *(const float2*)&WQ[(d0 + d) * HD + 2 * cp];
        const float2 wk = *(const float2*)&WK[(d0 + d) * HD + 2 * cp];
        const float2 wv = *(const float2*)&WV[(d0 + d) * HD + 2 * cp];
        #pragma unroll
        for (int r = 0; r < QR; r++) {
            const float hx = sh[r][d0 + d];
            acc[0][r][0] = fmaf(hx, wq.x, acc[0][r][0]);
            acc[0][r][1] = fmaf(hx, wq.y, acc[0][r][1]);
            acc[1][r][0] = fmaf(hx, wk.x, acc[1][r][0]);
            acc[1][r][1] = fmaf(hx, wk.y, acc[1][r][1]);
            acc[2][r][0] = fmaf(hx, wv.x, acc[2][r][0]);
            acc[2][r][1] = fmaf(hx, wv.y, acc[2][r][1]);
        }
    }
    if (dq > 0) {
        #pragma unroll
        for (int m = 0; m < 3; m++)
            #pragma unroll
            for (int r = 0; r < QR; r++)
                *(float2*)&sp[m][dq - 1][r][2 * cp] = make_float2(acc[m][r][0], acc[m][r][1]);
    }
    __syncthreads();
    if (dq == 0) {
        #pragma unroll
        for (int r = 0; r < QR; r++) {
            float qx = acc[0][r][0], qy = acc[0][r][1];
            float kx = acc[1][r][0], ky = acc[1][r][1];
            float vx = acc[2][r][0], vy = acc[2][r][1];
            #pragma unroll
            for (int s = 0; s < 3; s++) {
                qx += sp[0][s][r][2 * cp]; qy += sp[0][s][r][2 * cp + 1];
                kx += sp[1][s][r][2 * cp]; ky += sp[1][s][r][2 * cp + 1];
                vx += sp[2][s][r][2 * cp]; vy += sp[2][s][r][2 * cp + 1];
            }
            *(float2*)&g_Q[(rb + r) * HD + 2 * cp] = make_float2(qx, qy);
            *(float2*)&g_K[(rb + r) * HD + 2 * cp] = make_float2(kx * 0.25f, ky * 0.25f);
            *(float2*)&g_V[(rb + r) * HD + 2 * cp] = make_float2(vx, vy);
        }
    }
}

// ---------------------------------------------------------------------------
// Kernel 2: fused HMMA attention, fragment-domain reduction.
//   One CTA per (b,i), 256 threads (8 warps), 3 CTAs/SM.
//   S[256j x 256n] = fp16(e) @ W_hi^T   (single-term fp16, fp32 accum)
//   cols n<128: E2 scores; n>=128: E.
// ---------------------------------------------------------------------------
__global__ __launch_bounds__(256, 3)
void attn_mma_kernel(
    const float* __restrict__ e,
    const float* __restrict__ mask,
    float* __restrict__ out)
{
    extern __shared__ char smem[];
    const uint32_t sbase = smem_u32(smem);
    const int t   = threadIdx.x;
    const int wid = t >> 5;
    const int lid = t & 31;
    const int gid = lid >> 2;        // 0..7
    const int tig = lid & 3;         // 0..3
    const int bi  = blockIdx.x;
    const int b   = bi >> 8;
    const int i   = bi & 255;

    float* sQKv  = (float*)(smem + SM_QK);
    float* sAmv  = (float*)(smem + SM_AM);
    float* sQrow = (float*)(smem + SM_QROW);
    float* sWden = (float*)(smem + SM_WDEN);
    float* sWout = (float*)(smem + SM_WOUT);

    // ---- load W_hi (fp16) into SW128 smem: [256 rows x 128B] ----
    {
        const int ch = t & 7;          // 16B chunk within 128B row
        const int r0 = t >> 3;         // 32 rows per iteration
        #pragma unroll
        for (int it = 0; it < 8; it++) {
            const int row = it * 32 + r0;
            const uint32_t off = SMEM_SWZ(row * 128 + ch * 16);
            *(uint4*)(smem + SM_B + off) = ((const uint4*)g_Bh)[row * 8 + ch];
        }
    }

    // ---- A fragments direct from gmem: [mblk][kstep][4] (fp16, single term) ----
    uint32_t afr[2][4][4];
    {
        const float* __restrict__ eb = e + (size_t)bi * NN * DE;
        const int jb = wid * 32;
        #pragma unroll
        for (int mblk = 0; mblk < 2; mblk++) {
            const int r0 = jb + mblk * 16 + gid;
            #pragma unroll
            for (int ks = 0; ks < 4; ks++) {
                const int c0 = ks * 16 + tig * 2;
                afr[mblk][ks][0] = pack_h2(*(const float2*)(eb + r0 * DE + c0));
                afr[mblk][ks][1] = pack_h2(*(const float2*)(eb + (r0 + 8) * DE + c0));
                afr[mblk][ks][2] = pack_h2(*(const float2*)(eb + r0 * DE + c0 + 8));
                afr[mblk][ks][3] = pack_h2(*(const float2*)(eb + (r0 + 8) * DE + c0 + 8));
            }
        }
    }

    // ---- mask products + Q row ----
    sAmv[t] = mask[b * NN + i] * mask[b * NN + t];
    if (t < HD) sQrow[t] = g_Q[(size_t)bi * HD + t];
    __syncthreads();

    // ---- QK scores (fp32 exact): thread t owns j = t ----
    {
        const float4* __restrict__ Kp = (const float4*)(g_K + ((size_t)b * NN + t) * HD);
        #pragma unroll
        for (int hh = 0; hh < NH; hh++) {
            float s_ = 0.f;
            #pragma unroll
            for (int kk = 0; kk < DK / 4; kk++) {
                const float4 kv = Kp[hh * (DK / 4) + kk];
                const float* qp = &sQrow[hh * DK + kk * 4];
                s_ += kv.x * qp[0] + kv.y * qp[1] + kv.z * qp[2] + kv.w * qp[3];
            }
            sQKv[t * 9 + hh] = s_;
        }
    }
    __syncthreads();

    float am4[2][2];
    int   jrow[2][2];
    #pragma unroll
    for (int mblk = 0; mblk < 2; mblk++) {
        #pragma unroll
        for (int uh = 0; uh < 2; uh++) {
            jrow[mblk][uh] = wid * 32 + mblk * 16 + gid + uh * 8;
            am4[mblk][uh]  = sAmv[jrow[mblk][uh]];
        }
    }

    // ldmatrix lane roles: sel 0/1 -> score cols (k0-7 / k8-15), sel 2/3 -> E cols
    const int sel = lid >> 3;
    const int r8  = lid & 7;
    const int nsel = (sel >= 2) ? 128 : 0;
    const uint32_t koff16 = (sel & 1) * 16;
    const float* __restrict__ Vb = g_V + (size_t)b * NN * HD;

    // ---- main loop: 16 col-groups, no block barriers ----
    for (int h0 = 0; h0 < HD; h0 += 64) {
        #pragma unroll 1
        for (int cg = 0; cg < 8; cg++) {
            float accS[2][4] = {{0.f,0.f,0.f,0.f},{0.f,0.f,0.f,0.f}};
            float accE[2][4] = {{0.f,0.f,0.f,0.f},{0.f,0.f,0.f,0.f}};
            const int nrow = h0 + cg * 8 + r8 + nsel;
            const uint32_t rowbase = sbase + SM_B + (uint32_t)nrow * 128;
            const uint32_t xkey = ((uint32_t)nrow & 7) << 4;
            #pragma unroll
            for (int ks = 0; ks < 4; ks++) {
                const uint32_t addr = rowbase + (((uint32_t)ks * 32 + koff16) ^ xkey);
                uint32_t bh[4];
                ldmat_x4(bh, addr);
                #pragma unroll
                for (int mblk = 0; mblk < 2; mblk++) {
                    mma16816(accS[mblk], afr[mblk][ks], bh + 0);  // e @ W_hi (scores)
                    mma16816(accE[mblk], afr[mblk][ks], bh + 2);  // e @ W_hi (E)
                }
            }
            // fragment epilogue: head constant within cg; float2 V loads
            const int head = (h0 + cg * 8) >> 4;
            const int cbase = h0 + cg * 8 + tig * 2;
            float den0 = 0.f, den1 = 0.f, out0 = 0.f, out1 = 0.f;
            #pragma unroll
            for (int mblk = 0; mblk < 2; mblk++) {
                #pragma unroll
                for (int uh = 0; uh < 2; uh++) {
                    const int j  = jrow[mblk][uh];
                    const float qk = sQKv[j * 9 + head];
                    const float am = am4[mblk][uh];
                    const float2 vv = *(const float2*)&Vb[(size_t)j * HD + cbase];

                    float s0 = qk + accS[mblk][uh * 2];
                    s0 = fminf(5.f, fmaxf(-5.f, s0));
                    const float p0 = __expf(s0) * am;
                    den0 += p0;
                    out0 += p0 * am * (vv.x + accE[mblk][uh * 2]);

                    float s1 = qk + accS[mblk][uh * 2 + 1];
                    s1 = fminf(5.f, fmaxf(-5.f, s1));
                    const float p1 = __expf(s1) * am;
                    den1 += p1;
                    out1 += p1 * am * (vv.y + accE[mblk][uh * 2 + 1]);
                }
            }
            #pragma unroll
            for (int m_ = 4; m_ <= 16; m_ <<= 1) {
                den0 += __shfl_xor_sync(0xffffffffu, den0, m_);
                den1 += __shfl_xor_sync(0xffffffffu, den1, m_);
                out0 += __shfl_xor_sync(0xffffffffu, out0, m_);
                out1 += __shfl_xor_sync(0xffffffffu, out1, m_);
            }
            if (gid == 0) {
                *(float2*)&sWden[wid * 128 + cbase] = make_float2(den0, den1);
                *(float2*)&sWout[wid * 128 + cbase] = make_float2(out0, out1);
            }
        }
    }
    __syncthreads();

    // ---- final cross-warp combine ----
    if (t < HD) {
        float D_ = 0.f, O_ = 0.f;
        #pragma unroll
        for (int w = 0; w < 8; w++) {
            D_ += sWden[w * 128 + t];
            O_ += sWout[w * 128 + t];
        }
        out[(size_t)bi * HD + t] = O_ / fmaxf(D_, 1e-6f);
    }
}

// ---------------------------------------------------------------------------
// Launch
// ---------------------------------------------------------------------------
extern "C" void kernel_launch(void* const* d_in, const int* in_sizes, int n_in,
                              void* d_out, int out_size)
{
    const float* h    = (const float*)d_in[0];
    const float* e    = (const float*)d_in[1];
    const float* mask = (const float*)d_in[2];
    const float* WQ   = (const float*)d_in[3];
    const float* WK   = (const float*)d_in[4];
    const float* WV   = (const float*)d_in[5];
    const float* WE   = (const float*)d_in[6];
    const float* WE2  = (const float*)d_in[7];
    float* out = (float*)d_out;

    cudaFuncSetAttribute(attn_mma_kernel,
                         cudaFuncAttributeMaxDynamicSharedMemorySize, SMEM_TOTAL);

    prep_kernel<<<QKV_BLOCKS + 64, 256>>>(h, WQ, WK, WV, WE, WE2);
    attn_mma_kernel<<<BB * NN, 256, SMEM_TOTAL>>>(e, mask, out);
}